// round 6
// baseline (speedup 1.0000x reference)
#include <cuda_runtime.h>

#define TPB  32     // threads per CTA
#define NB   64     // batches per CTA (2 per thread)
#define NC   2      // chains (batches) per thread
#define STR  65     // padded shared row stride
#define NN   64     // number of unknowns (N)
#define NP   65     // N + 1
#define LAM3  1e-4f
#define RIDGE 1e-4f

__host__ __device__ __forceinline__ float C0f(int a) {
    return (a == 1) ? 10.f : (a == 2) ? 19.f :
           (a <= 61) ? 20.f : (a == 62) ? 19.f : (a == 63) ? 10.f : 1.f;
}
__host__ __device__ __forceinline__ float C1f(int a) {
    return (a == 1) ? -12.f : (a <= 61) ? -15.f :
           (a == 62) ? -12.f : (a == 63) ? -3.f : 0.f;
}
__host__ __device__ __forceinline__ float C2f(int a) {
    return (a <= 61) ? 6.f : (a == 62) ? 3.f : 0.f;
}
__host__ __device__ __forceinline__ float C3f(int a) {
    return (a <= 61) ? -1.f : 0.f;
}

// Shared layout:
//  s4   : NN*NB float4    packed (L1*inv, L2*inv, L3*inv, z*inv)
//  sth  : 67 rows * STR   theta (+2 zero pad rows)
//  sgx  : 66 rows * STR   2*dxy.x (+2 pad)
//  sgy  : 66 rows * STR   2*dxy.y (+2 pad)
//  sou  : NP rows * STR   output staging
//  sCb4 : NN float4       band constants (broadcast)
#define S4_F4    (NN*NB)
#define STH_F    (67*STR)
#define SGX_F    (66*STR)
#define SOU_F    (NP*STR)
#define SMEM_BYTES (S4_F4*16 + (STH_F + 2*SGX_F + SOU_F)*4 + NN*16)

__global__ __launch_bounds__(TPB, 1) void AlpamayoR1_solve_kernel(
    const float* __restrict__ dxy,
    const float* __restrict__ theta,
    const float* __restrict__ v0,
    float* __restrict__ out, int B)
{
    extern __shared__ float4 smem4[];
    float4* s4   = smem4;
    float*  sth  = (float*)(s4 + S4_F4);
    float*  sgx  = sth + STH_F;
    float*  sgy  = sgx + SGX_F;
    float*  sou  = sgy + SGX_F;
    float4* sCb4 = (float4*)(sou + SOU_F);

    const int t  = threadIdx.x;
    const int b0 = blockIdx.x * NB;

    // ---- band constant table (columns a = 1..64) ----
    for (int a0 = t; a0 < NN; a0 += TPB) {
        int a = a0 + 1;
        float base = (a0 < NN - 1) ? 2.f : 1.f;
        sCb4[a0] = make_float4(base + LAM3 * C0f(a) + RIDGE,
                               LAM3 * C1f(a), LAM3 * C2f(a), LAM3 * C3f(a));
    }

    // ---- zero pad rows ----
    #pragma unroll
    for (int c = 0; c < 2; c++) {
        int col = t + 32 * c;
        sth[65 * STR + col] = 0.f;
        sth[66 * STR + col] = 0.f;
        sgx[64 * STR + col] = 0.f;
        sgx[65 * STR + col] = 0.f;
        sgy[64 * STR + col] = 0.f;
        sgy[65 * STR + col] = 0.f;
    }

    // ---- theta staging: float4 coalesced loads, scattered scalar STS ----
    {
        const float4* th4 = (const float4*)(theta + (size_t)b0 * NP);
        for (int i = t; i < (NB * NP) / 4; i += TPB) {   // 1040 float4
            float4 v = th4[i];
            int f = 4 * i;
            int bl0 = f / NP, k0 = f - bl0 * NP;
            sth[k0 * STR + bl0] = v.x;
            int f1 = f + 1; int bl1 = f1 / NP, k1 = f1 - bl1 * NP;
            sth[k1 * STR + bl1] = v.y;
            int f2 = f + 2; int bl2 = f2 / NP, k2 = f2 - bl2 * NP;
            sth[k2 * STR + bl2] = v.z;
            int f3 = f + 3; int bl3 = f3 / NP, k3 = f3 - bl3 * NP;
            sth[k3 * STR + bl3] = v.w;
        }
    }
    // ---- dxy staging ----
    {
        const float4* dx4 = (const float4*)(dxy + (size_t)b0 * NN * 2);
        #pragma unroll 4
        for (int i = t; i < (NB * NN) / 2; i += TPB) {   // 2048 float4
            float4 v = dx4[i];
            int bl = i >> 5;
            int s0 = (i & 31) * 2;
            sgx[s0 * STR + bl]       = 2.f * v.x;
            sgy[s0 * STR + bl]       = 2.f * v.y;
            sgx[(s0 + 1) * STR + bl] = 2.f * v.z;
            sgy[(s0 + 1) * STR + bl] = 2.f * v.w;
        }
    }
    float v0v[NC];
    #pragma unroll
    for (int c = 0; c < NC; c++) v0v[c] = v0[b0 + t + 32 * c];
    __syncthreads();

    // ---- prologue (both chains) ----
    float e0[NC], cA[NC], sA[NC], gxj[NC], gyj[NC], thn[NC], gxn[NC], gyn[NC];
    #pragma unroll
    for (int c = 0; c < NC; c++) {
        int col = t + 32 * c;
        float th0 = sth[col];       float s0v, c0v; __sincosf(th0, &s0v, &c0v);
        float th1 = sth[STR + col]; float s1v, c1v; __sincosf(th1, &s1v, &c1v);
        cA[c] = c1v; sA[c] = s1v;
        e0[c] = c0v * c1v + s0v * s1v;
        gxj[c] = sgx[col];  gyj[c] = sgy[col];
        thn[c] = sth[2 * STR + col];
        gxn[c] = sgx[STR + col];
        gyn[c] = sgy[STR + col];
    }

    // rolling Cholesky state, both chains
    float L1p[NC]  = {0.f, 0.f};
    float L2p1[NC] = {0.f, 0.f}, L2p2[NC] = {0.f, 0.f};
    float L3p1[NC] = {0.f, 0.f}, L3p2[NC] = {0.f, 0.f}, L3p3[NC] = {0.f, 0.f};
    float zp1[NC]  = {0.f, 0.f}, zp2[NC]  = {0.f, 0.f}, zp3[NC]  = {0.f, 0.f};

    #pragma unroll 4
    for (int j = 0; j < NN; ++j) {
        float4 cb = sCb4[j];             // broadcast
        #pragma unroll
        for (int c = 0; c < NC; c++) {
            int col = t + 32 * c;
            float sB, cB; __sincosf(thn[c], &sB, &cB);

            // prefetch next iteration (pad rows make these safe)
            float thn2 = sth[(j + 3) * STR + col];
            float gxn2 = sgx[(j + 2) * STR + col];
            float gyn2 = sgy[(j + 2) * STR + col];

            float e1  = cA[c] * cB + sA[c] * sB;
            if (j == NN - 1) e1 = 0.f;
            float rhs = cA[c] * (gxj[c] + gxn[c]) + sA[c] * (gyj[c] + gyn[c]);
            if (j == 0) rhs -= (e0[c] - 3.f * LAM3) * v0v[c];
            if (j == 1) rhs -= 3.f * LAM3 * v0v[c];
            if (j == 2) rhs += LAM3 * v0v[c];

            float d   = cb.x - L1p[c] * L1p[c] - L2p2[c] * L2p2[c] - L3p3[c] * L3p3[c];
            float inv = rsqrtf(d);

            float s1v = e1 + cb.y - L2p1[c] * L1p[c] - L3p2[c] * L2p2[c];
            float s2v = cb.z - L3p1[c] * L1p[c];
            float s3v = cb.w;

            float L1 = s1v * inv;
            float L2 = s2v * inv;
            float L3 = s3v * inv;
            float z  = (rhs - L1p[c] * zp1[c] - L2p2[c] * zp2[c] - L3p3[c] * zp3[c]) * inv;

            float4 pk;
            pk.x = L1 * inv; pk.y = L2 * inv; pk.z = L3 * inv; pk.w = z * inv;
            s4[j * NB + col] = pk;       // STS.128

            L3p3[c] = L3p2[c]; L3p2[c] = L3p1[c]; L3p1[c] = L3;
            L2p2[c] = L2p1[c]; L2p1[c] = L2;
            L1p[c]  = L1;
            zp3[c]  = zp2[c];  zp2[c]  = zp1[c];  zp1[c]  = z;
            cA[c] = cB; sA[c] = sB;
            gxj[c] = gxn[c]; gyj[c] = gyn[c];
            thn[c] = thn2; gxn[c] = gxn2; gyn[c] = gyn2;
        }
    }

    // ---- back substitution, both chains interleaved ----
    {
        float y1[NC] = {0.f, 0.f}, y2[NC] = {0.f, 0.f}, y3[NC] = {0.f, 0.f};
        #pragma unroll 4
        for (int j = NN - 1; j >= 0; --j) {
            #pragma unroll
            for (int c = 0; c < NC; c++) {
                int col = t + 32 * c;
                float4 pk = s4[j * NB + col];
                float tmp = pk.w - pk.y * y2[c] - pk.z * y3[c];
                float y   = tmp - pk.x * y1[c];
                sou[(j + 1) * STR + col] = y;
                y3[c] = y2[c]; y2[c] = y1[c]; y1[c] = y;
            }
        }
        #pragma unroll
        for (int c = 0; c < NC; c++) sou[t + 32 * c] = v0v[c];
    }
    __syncthreads();

    // ---- coalesced float4 store ----
    {
        float4* out4 = (float4*)(out + (size_t)b0 * NP);
        for (int i = t; i < (NB * NP) / 4; i += TPB) {
            int f = 4 * i;
            int bl0 = f / NP, k0 = f - bl0 * NP;
            int f1 = f + 1; int bl1 = f1 / NP, k1 = f1 - bl1 * NP;
            int f2 = f + 2; int bl2 = f2 / NP, k2 = f2 - bl2 * NP;
            int f3 = f + 3; int bl3 = f3 / NP, k3 = f3 - bl3 * NP;
            float4 v;
            v.x = sou[k0 * STR + bl0];
            v.y = sou[k1 * STR + bl1];
            v.z = sou[k2 * STR + bl2];
            v.w = sou[k3 * STR + bl3];
            out4[i] = v;
        }
    }
}

extern "C" void kernel_launch(void* const* d_in, const int* in_sizes, int n_in,
                              void* d_out, int out_size) {
    const float* dxy   = (const float*)d_in[0];
    const float* theta = (const float*)d_in[1];
    const float* v0    = (const float*)d_in[2];
    float* out = (float*)d_out;
    int B = in_sizes[2];

    cudaFuncSetAttribute(AlpamayoR1_solve_kernel,
                         cudaFuncAttributeMaxDynamicSharedMemorySize, SMEM_BYTES);
    int grid = (B + NB - 1) / NB;
    AlpamayoR1_solve_kernel<<<grid, TPB, SMEM_BYTES>>>(dxy, theta, v0, out, B);
}

// round 7
// speedup vs baseline: 1.3300x; 1.3300x over previous
#include <cuda_runtime.h>

#define BLK  64     // batches per CTA == threads per CTA
#define STR  65     // padded shared row stride
#define NN   64     // number of unknowns (N)
#define NP   65     // N + 1
#define LAM3  1e-4f
#define RIDGE 1e-4f

// DTD band coefficients, a = column index in [1, 64]:
__host__ __device__ __forceinline__ float C0f(int a) {
    return (a == 1) ? 10.f : (a == 2) ? 19.f :
           (a <= 61) ? 20.f : (a == 62) ? 19.f : (a == 63) ? 10.f : 1.f;
}
__host__ __device__ __forceinline__ float C1f(int a) {
    return (a == 1) ? -12.f : (a <= 61) ? -15.f :
           (a == 62) ? -12.f : (a == 63) ? -3.f : 0.f;
}
__host__ __device__ __forceinline__ float C2f(int a) {
    return (a <= 61) ? 6.f : (a == 62) ? 3.f : 0.f;
}
__host__ __device__ __forceinline__ float C3f(int a) {
    return (a <= 61) ? -1.f : 0.f;
}

// Shared layout:
//  s4   : NN*BLK float4   packed (L1*inv, L2*inv, L3*inv, z*inv)
//  sth  : NP rows * STR   theta staging
//  sgx  : NN rows * STR   2*dxy.x
//  sgy  : NN rows * STR   2*dxy.y
//  sou  : NP rows * STR   output staging
#define S4_F4    (NN*BLK)
#define SMEM_BYTES (S4_F4*16 + (NP*STR + 2*NN*STR + NP*STR)*4)

__global__ __launch_bounds__(BLK, 1) void AlpamayoR1_solve_kernel(
    const float* __restrict__ dxy,
    const float* __restrict__ theta,
    const float* __restrict__ v0,
    float* __restrict__ out, int B)
{
    extern __shared__ float4 smem4[];
    float4* s4  = smem4;
    float*  sth = (float*)(s4 + S4_F4);
    float*  sgx = sth + NP*STR;
    float*  sgy = sgx + NN*STR;
    float*  sou = sgy + NN*STR;

    const int t  = threadIdx.x;
    const int b0 = blockIdx.x * BLK;

    // ---- coalesced float4 loads, transpose into padded shared ----
    {
        const float4* th4 = (const float4*)(theta + (size_t)b0 * NP);
        for (int i = t; i < (BLK * NP) / 4; i += BLK) {
            float4 v = th4[i];
            int f = 4 * i;
            int bl0 = f / NP, k0 = f - bl0 * NP;
            sth[k0 * STR + bl0] = v.x;
            int f1 = f + 1; int bl1 = f1 / NP, k1 = f1 - bl1 * NP;
            sth[k1 * STR + bl1] = v.y;
            int f2 = f + 2; int bl2 = f2 / NP, k2 = f2 - bl2 * NP;
            sth[k2 * STR + bl2] = v.z;
            int f3 = f + 3; int bl3 = f3 / NP, k3 = f3 - bl3 * NP;
            sth[k3 * STR + bl3] = v.w;
        }
    }
    {
        const float4* dx4 = (const float4*)(dxy + (size_t)b0 * NN * 2);
        #pragma unroll 4
        for (int i = t; i < (BLK * NN) / 2; i += BLK) {
            float4 v = dx4[i];
            int bl = i >> 5;
            int s0 = (i & 31) * 2;
            sgx[s0 * STR + bl]       = 2.f * v.x;
            sgy[s0 * STR + bl]       = 2.f * v.y;
            sgx[(s0 + 1) * STR + bl] = 2.f * v.z;
            sgy[(s0 + 1) * STR + bl] = 2.f * v.w;
        }
    }
    float v0v = v0[b0 + t];
    __syncthreads();

    // ---- Phase 1 (parallel, ILP-rich): sincos -> e[], rh[] in REGISTERS ----
    float e[NN];    // e[j] = cos(th_j)cos(th_j+1) + sin(th_j)sin(th_j+1)
    float rh[NN];   // fully assembled rhs_j
    {
        float thp = sth[t];
        float sp, cp; __sincosf(thp, &sp, &cp);
        float gxp = sgx[t];
        float gyp = sgy[t];
        #pragma unroll
        for (int k = 1; k <= NN; ++k) {
            float th = sth[k * STR + t];
            float s, c; __sincosf(th, &s, &c);
            float gx = 0.f, gy = 0.f;
            if (k < NN) { gx = sgx[k * STR + t]; gy = sgy[k * STR + t]; }
            e [k - 1] = cp * c + sp * s;
            rh[k - 1] = c * (gxp + gx) + s * (gyp + gy);
            cp = c; sp = s; gxp = gx; gyp = gy;
        }
        rh[0] -= (e[0] - 3.f * LAM3) * v0v;
        rh[1] -= 3.f * LAM3 * v0v;
        rh[2] += LAM3 * v0v;
    }

    // ---- Phase 2 (serial): register-only band Cholesky + forward solve ----
    {
        float L1p  = 0.f;
        float L2p1 = 0.f, L2p2 = 0.f;
        float L3p1 = 0.f, L3p2 = 0.f, L3p3 = 0.f;
        float zp1  = 0.f, zp2  = 0.f, zp3  = 0.f;

        #pragma unroll
        for (int j = 0; j < NN; ++j) {
            const float a0 = ((j < NN - 1) ? 2.f : 1.f) + LAM3 * C0f(j + 1) + RIDGE;
            float d   = a0 - L1p * L1p - L2p2 * L2p2 - L3p3 * L3p3;
            float inv = rsqrtf(d);

            float s1v = (j < NN - 1)
                      ? (e[j + 1] + LAM3 * C1f(j + 1) - L2p1 * L1p - L3p2 * L2p2)
                      : 0.f;
            float s2v = (j < NN - 2) ? (LAM3 * C2f(j + 1) - L3p1 * L1p) : 0.f;
            float s3v = (j < NN - 3) ? (LAM3 * C3f(j + 1)) : 0.f;

            float L1 = s1v * inv;
            float L2 = s2v * inv;
            float L3 = s3v * inv;
            float z  = (rh[j] - L1p * zp1 - L2p2 * zp2 - L3p3 * zp3) * inv;

            float4 pk;
            pk.x = L1 * inv; pk.y = L2 * inv; pk.z = L3 * inv; pk.w = z * inv;
            s4[j * BLK + t] = pk;        // STS.128, off the chain

            L3p3 = L3p2; L3p2 = L3p1; L3p1 = L3;
            L2p2 = L2p1; L2p1 = L2;
            L1p  = L1;
            zp3  = zp2;  zp2  = zp1;  zp1  = z;
        }
    }

    // ---- Phase 3: back substitution (LDS.128/step, shallow chain) ----
    {
        float y1 = 0.f, y2 = 0.f, y3 = 0.f;
        #pragma unroll 8
        for (int j = NN - 1; j >= 0; --j) {
            float4 pk = s4[j * BLK + t];
            float tmp = pk.w - pk.y * y2 - pk.z * y3;   // independent of y1
            float y   = tmp - pk.x * y1;
            sou[(j + 1) * STR + t] = y;
            y3 = y2; y2 = y1; y1 = y;
        }
        sou[t] = v0v;
    }
    __syncthreads();

    // ---- coalesced float4 store ----
    {
        float4* out4 = (float4*)(out + (size_t)b0 * NP);
        for (int i = t; i < (BLK * NP) / 4; i += BLK) {
            int f = 4 * i;
            int bl0 = f / NP, k0 = f - bl0 * NP;
            int f1 = f + 1; int bl1 = f1 / NP, k1 = f1 - bl1 * NP;
            int f2 = f + 2; int bl2 = f2 / NP, k2 = f2 - bl2 * NP;
            int f3 = f + 3; int bl3 = f3 / NP, k3 = f3 - bl3 * NP;
            float4 v;
            v.x = sou[k0 * STR + bl0];
            v.y = sou[k1 * STR + bl1];
            v.z = sou[k2 * STR + bl2];
            v.w = sou[k3 * STR + bl3];
            out4[i] = v;
        }
    }
}

extern "C" void kernel_launch(void* const* d_in, const int* in_sizes, int n_in,
                              void* d_out, int out_size) {
    const float* dxy   = (const float*)d_in[0];
    const float* theta = (const float*)d_in[1];
    const float* v0    = (const float*)d_in[2];
    float* out = (float*)d_out;
    int B = in_sizes[2];

    cudaFuncSetAttribute(AlpamayoR1_solve_kernel,
                         cudaFuncAttributeMaxDynamicSharedMemorySize, SMEM_BYTES);
    int grid = (B + BLK - 1) / BLK;
    AlpamayoR1_solve_kernel<<<grid, BLK, SMEM_BYTES>>>(dxy, theta, v0, out, B);
}

// round 8
// speedup vs baseline: 1.9504x; 1.4665x over previous
#include <cuda_runtime.h>

#define TPB  128    // threads per CTA: warps 0-1 = "top", warps 2-3 = "bottom"
#define NB   64     // batches per CTA (2 threads each)
#define STR  65     // padded shared row stride
#define NN   64     // unknowns
#define NP   65
#define LAM3  1e-4f
#define RIDGE 1e-4f

// DTD band coefficients, a in [1,64]:
__host__ __device__ __forceinline__ constexpr float C0f(int a) {
    return (a == 1) ? 10.f : (a == 2) ? 19.f :
           (a <= 61) ? 20.f : (a == 62) ? 19.f : (a == 63) ? 10.f : 1.f;
}
__host__ __device__ __forceinline__ constexpr float C1f(int a) {
    return (a == 1) ? -12.f : (a <= 61) ? -15.f :
           (a == 62) ? -12.f : (a == 63) ? -3.f : 0.f;
}
__host__ __device__ __forceinline__ constexpr float C2f(int a) {
    return (a <= 61) ? 6.f : (a == 62) ? 3.f : 0.f;
}
__host__ __device__ __forceinline__ constexpr float C3f(int a) {
    return (a <= 61) ? -1.f : 0.f;
}
// diag of lhs at var p (0..63):
__host__ __device__ __forceinline__ constexpr float diagf(int p) {
    return ((p < 63) ? 2.f : 1.f) + LAM3 * C0f(p + 1) + RIDGE;
}

// Shared layout:
//  s4  : 64 rows * NB float4  (rows 0..30 top pk, rows 32..61 bottom pk)
//  sth : 65 rows * STR        theta
//  sgx : 64 rows * STR        2*dxy.x
//  sgy : 64 rows * STR        2*dxy.y
//  sou : 65 rows * STR        output staging
//  sxc : 18 * NB              central exchange (top items 0..8, bottom 9..17)
#define S4_F4    (64*NB)
#define SMEM_BYTES (S4_F4*16 + (65*STR + 2*64*STR + 65*STR + 18*NB)*4)

__global__ __launch_bounds__(TPB, 1) void AlpamayoR1_solve_kernel(
    const float* __restrict__ dxy,
    const float* __restrict__ theta,
    const float* __restrict__ v0,
    float* __restrict__ out, int B)
{
    extern __shared__ float4 smem4[];
    float4* s4  = smem4;
    float*  sth = (float*)(s4 + S4_F4);
    float*  sgx = sth + 65*STR;
    float*  sgy = sgx + 64*STR;
    float*  sou = sgy + 64*STR;
    float*  sxc = sou + 65*STR;

    const int t  = threadIdx.x;
    const int b0 = blockIdx.x * NB;
    const bool isTop = (t < 64);
    const int col = isTop ? t : (t - 64);   // local batch

    // ---- staging: coalesced float4 loads, transpose into shared ----
    {
        const float4* th4 = (const float4*)(theta + (size_t)b0 * NP);
        for (int i = t; i < (NB * NP) / 4; i += TPB) {   // 1040
            float4 v = th4[i];
            int f = 4 * i;
            int bl0 = f / NP, k0 = f - bl0 * NP;
            sth[k0 * STR + bl0] = v.x;
            int f1 = f + 1; int bl1 = f1 / NP, k1 = f1 - bl1 * NP;
            sth[k1 * STR + bl1] = v.y;
            int f2 = f + 2; int bl2 = f2 / NP, k2 = f2 - bl2 * NP;
            sth[k2 * STR + bl2] = v.z;
            int f3 = f + 3; int bl3 = f3 / NP, k3 = f3 - bl3 * NP;
            sth[k3 * STR + bl3] = v.w;
        }
        const float4* dx4 = (const float4*)(dxy + (size_t)b0 * NN * 2);
        #pragma unroll 4
        for (int i = t; i < (NB * NN) / 2; i += TPB) {   // 2048
            float4 v = dx4[i];
            int bl = i >> 5;
            int s0 = (i & 31) * 2;
            sgx[s0 * STR + bl]       = 2.f * v.x;
            sgy[s0 * STR + bl]       = 2.f * v.y;
            sgx[(s0 + 1) * STR + bl] = 2.f * v.z;
            sgy[(s0 + 1) * STR + bl] = 2.f * v.w;
        }
    }
    float v0v = 0.f;
    if (isTop) v0v = v0[b0 + col];
    __syncthreads();

    float x31, x32, x33;   // central unknowns (vars 31,32,33)

    if (isTop) {
        // ======== TOP HALF: vars 0..30, central assembly ========
        float e[34], rh[34];            // e[0..33], rh[0..33]
        {
            float thp = sth[col];
            float sp, cp; __sincosf(thp, &sp, &cp);
            float gxp = sgx[col], gyp = sgy[col];
            #pragma unroll
            for (int k = 1; k <= 34; ++k) {
                float th = sth[k * STR + col];
                float s, c; __sincosf(th, &s, &c);
                float gx = sgx[k * STR + col];
                float gy = sgy[k * STR + col];
                e [k - 1] = cp * c + sp * s;
                rh[k - 1] = c * (gxp + gx) + s * (gyp + gy);
                cp = c; sp = s; gxp = gx; gyp = gy;
            }
            rh[0] -= (e[0] - 3.f * LAM3) * v0v;
            rh[1] -= 3.f * LAM3 * v0v;
            rh[2] += LAM3 * v0v;
        }

        float L1p = 0.f, L2p1 = 0.f, L2p2 = 0.f;
        float L3p1 = 0.f, L3p2 = 0.f, L3p3 = 0.f;
        float zp1 = 0.f, zp2 = 0.f, zp3 = 0.f;
        #pragma unroll
        for (int j = 0; j <= 30; ++j) {
            float a0  = diagf(j);
            float d   = a0 - L1p * L1p - L2p2 * L2p2 - L3p3 * L3p3;
            float inv = rsqrtf(d);
            float s1v = e[j + 1] + LAM3 * C1f(j + 1) - L2p1 * L1p - L3p2 * L2p2;
            float s2v = LAM3 * C2f(j + 1) - L3p1 * L1p;
            float s3v = LAM3 * C3f(j + 1);
            float L1 = s1v * inv, L2 = s2v * inv, L3 = s3v * inv;
            float z  = (rh[j] - L1p * zp1 - L2p2 * zp2 - L3p3 * zp3) * inv;
            float4 pk; pk.x = L1 * inv; pk.y = L2 * inv; pk.z = L3 * inv; pk.w = z * inv;
            s4[j * NB + col] = pk;
            L3p3 = L3p2; L3p2 = L3p1; L3p1 = L3;
            L2p2 = L2p1; L2p1 = L2; L1p = L1;
            zp3 = zp2; zp2 = zp1; zp1 = z;
        }
        // central assembly (A_c minus top contributions)
        sxc[0 * NB + col] = diagf(31) - (L1p*L1p + L2p2*L2p2 + L3p3*L3p3);          // S11t
        sxc[1 * NB + col] = e[32] + LAM3 * C1f(32) - (L2p1*L1p + L3p2*L2p2);        // S12t
        sxc[2 * NB + col] = LAM3 * C2f(32) - (L3p1*L1p);                            // S13t
        sxc[3 * NB + col] = diagf(32) - (L2p1*L2p1 + L3p2*L3p2);                    // S22t
        sxc[4 * NB + col] = e[33] + LAM3 * C1f(33) - (L3p1*L2p1);                   // S23t
        sxc[5 * NB + col] = diagf(33) - (L3p1*L3p1);                                // S33t
        sxc[6 * NB + col] = rh[31] - (L1p*zp1 + L2p2*zp2 + L3p3*zp3);               // r1t
        sxc[7 * NB + col] = rh[32] - (L2p1*zp1 + L3p2*zp2);                         // r2t
        sxc[8 * NB + col] = rh[33] - (L3p1*zp1);                                    // r3t
        __syncthreads();

        // central 3x3 solve
        float S11 = sxc[0*NB+col] - sxc[ 9*NB+col];
        float S12 = sxc[1*NB+col] - sxc[10*NB+col];
        float S13 = sxc[2*NB+col] - sxc[11*NB+col];
        float S22 = sxc[3*NB+col] - sxc[12*NB+col];
        float S23 = sxc[4*NB+col] - sxc[13*NB+col];
        float S33 = sxc[5*NB+col] - sxc[14*NB+col];
        float r1  = sxc[6*NB+col] - sxc[15*NB+col];
        float r2  = sxc[7*NB+col] - sxc[16*NB+col];
        float r3  = sxc[8*NB+col] - sxc[17*NB+col];
        float i1 = rsqrtf(S11);
        float l21 = S12 * i1, l31 = S13 * i1;
        float i2 = rsqrtf(S22 - l21 * l21);
        float l32 = (S23 - l31 * l21) * i2;
        float i3 = rsqrtf(S33 - l31 * l31 - l32 * l32);
        float u1 = r1 * i1;
        float u2 = (r2 - l21 * u1) * i2;
        float u3 = (r3 - l31 * u1 - l32 * u2) * i3;
        x33 = u3 * i3;
        x32 = (u2 - l32 * x33) * i2;
        x31 = (u1 - l21 * x32 - l31 * x33) * i1;

        // back substitution for vars 30..0
        float y1 = x31, y2 = x32, y3 = x33;
        #pragma unroll
        for (int j = 30; j >= 0; --j) {
            float4 pk = s4[j * NB + col];
            float tmp = pk.w - pk.y * y2 - pk.z * y3;
            float y   = tmp - pk.x * y1;
            sou[(j + 1) * STR + col] = y;
            y3 = y2; y2 = y1; y1 = y;
        }
        sou[col] = v0v;
        sou[32 * STR + col] = x31;
        sou[33 * STR + col] = x32;
        sou[34 * STR + col] = x33;
    } else {
        // ======== BOTTOM HALF: vars 63..34 (reversed matrix) ========
        float ebt[30], rhb[30];   // ebt[i]=e[63-i], rhb[i]=rh[63-i], i=0..29
        {
            float thp = sth[64 * STR + col];     // theta_64
            float sp, cp; __sincosf(thp, &sp, &cp);
            float gxp = 0.f, gyp = 0.f;          // g_64 doesn't exist
            #pragma unroll
            for (int i = 0; i < 30; ++i) {
                int k = 64 - i;                  // pair (th_{k-1}, th_k)
                float th = sth[(k - 1) * STR + col];
                float s, c; __sincosf(th, &s, &c);
                float gx = sgx[(k - 1) * STR + col];
                float gy = sgy[(k - 1) * STR + col];
                ebt[i] = c * cp + s * sp;                    // e[k-1] = e[63-i]
                rhb[i] = cp * (gx + gxp) + sp * (gy + gyp);  // rh[k-1]
                cp = c; sp = s; gxp = gx; gyp = gy;
            }
        }

        float L1p = 0.f, L2p1 = 0.f, L2p2 = 0.f;
        float L3p1 = 0.f, L3p2 = 0.f, L3p3 = 0.f;
        float zp1 = 0.f, zp2 = 0.f, zp3 = 0.f;
        #pragma unroll
        for (int j = 0; j <= 29; ++j) {          // eliminates var 63-j
            float a0  = ((j == 0) ? 1.f : 2.f) + LAM3 * C0f(64 - j) + RIDGE;
            float d   = a0 - L1p * L1p - L2p2 * L2p2 - L3p3 * L3p3;
            float inv = rsqrtf(d);
            float s1v = ebt[j] + LAM3 * C1f(63 - j) - L2p1 * L1p - L3p2 * L2p2;
            float s2v = LAM3 * C2f(62 - j) - L3p1 * L1p;
            float s3v = LAM3 * C3f(61 - j);
            float L1 = s1v * inv, L2 = s2v * inv, L3 = s3v * inv;
            float z  = (rhb[j] - L1p * zp1 - L2p2 * zp2 - L3p3 * zp3) * inv;
            float4 pk; pk.x = L1 * inv; pk.y = L2 * inv; pk.z = L3 * inv; pk.w = z * inv;
            s4[(32 + j) * NB + col] = pk;
            L3p3 = L3p2; L3p2 = L3p1; L3p1 = L3;
            L2p2 = L2p1; L2p1 = L2; L1p = L1;
            zp3 = zp2; zp2 = zp1; zp1 = z;
        }
        // bottom contributions (reversed: rev rows 30,31,32 = orig 33,32,31)
        sxc[14 * NB + col] = L1p*L1p + L2p2*L2p2 + L3p3*L3p3;     // to S33
        sxc[13 * NB + col] = L2p1*L1p + L3p2*L2p2;                // to S23
        sxc[11 * NB + col] = L3p1*L1p;                            // to S13
        sxc[12 * NB + col] = L2p1*L2p1 + L3p2*L3p2;               // to S22
        sxc[10 * NB + col] = L3p1*L2p1;                           // to S12
        sxc[ 9 * NB + col] = L3p1*L3p1;                           // to S11
        sxc[17 * NB + col] = L1p*zp1 + L2p2*zp2 + L3p3*zp3;       // to r3
        sxc[16 * NB + col] = L2p1*zp1 + L3p2*zp2;                 // to r2
        sxc[15 * NB + col] = L3p1*zp1;                            // to r1
        __syncthreads();

        // central 3x3 solve (redundant with top)
        float S11 = sxc[0*NB+col] - sxc[ 9*NB+col];
        float S12 = sxc[1*NB+col] - sxc[10*NB+col];
        float S13 = sxc[2*NB+col] - sxc[11*NB+col];
        float S22 = sxc[3*NB+col] - sxc[12*NB+col];
        float S23 = sxc[4*NB+col] - sxc[13*NB+col];
        float S33 = sxc[5*NB+col] - sxc[14*NB+col];
        float r1  = sxc[6*NB+col] - sxc[15*NB+col];
        float r2  = sxc[7*NB+col] - sxc[16*NB+col];
        float r3  = sxc[8*NB+col] - sxc[17*NB+col];
        float i1 = rsqrtf(S11);
        float l21 = S12 * i1, l31 = S13 * i1;
        float i2 = rsqrtf(S22 - l21 * l21);
        float l32 = (S23 - l31 * l21) * i2;
        float i3 = rsqrtf(S33 - l31 * l31 - l32 * l32);
        float u1 = r1 * i1;
        float u2 = (r2 - l21 * u1) * i2;
        float u3 = (r3 - l31 * u1 - l32 * u2) * i3;
        x33 = u3 * i3;
        x32 = (u2 - l32 * x33) * i2;
        x31 = (u1 - l21 * x32 - l31 * x33) * i1;

        // back substitution for vars 34..63 (rev coords)
        float y1 = x33, y2 = x32, y3 = x31;   // x'_{30},x'_{31},x'_{32}
        #pragma unroll
        for (int j = 29; j >= 0; --j) {
            float4 pk = s4[(32 + j) * NB + col];
            float tmp = pk.w - pk.y * y2 - pk.z * y3;
            float y   = tmp - pk.x * y1;      // x'_j = x_{63-j}
            sou[(64 - j) * STR + col] = y;    // out index (63-j)+1
            y3 = y2; y2 = y1; y1 = y;
        }
    }
    __syncthreads();

    // ---- coalesced float4 store ----
    {
        float4* out4 = (float4*)(out + (size_t)b0 * NP);
        for (int i = t; i < (NB * NP) / 4; i += TPB) {
            int f = 4 * i;
            int bl0 = f / NP, k0 = f - bl0 * NP;
            int f1 = f + 1; int bl1 = f1 / NP, k1 = f1 - bl1 * NP;
            int f2 = f + 2; int bl2 = f2 / NP, k2 = f2 - bl2 * NP;
            int f3 = f + 3; int bl3 = f3 / NP, k3 = f3 - bl3 * NP;
            float4 v;
            v.x = sou[k0 * STR + bl0];
            v.y = sou[k1 * STR + bl1];
            v.z = sou[k2 * STR + bl2];
            v.w = sou[k3 * STR + bl3];
            out4[i] = v;
        }
    }
}

extern "C" void kernel_launch(void* const* d_in, const int* in_sizes, int n_in,
                              void* d_out, int out_size) {
    const float* dxy   = (const float*)d_in[0];
    const float* theta = (const float*)d_in[1];
    const float* v0    = (const float*)d_in[2];
    float* out = (float*)d_out;
    int B = in_sizes[2];

    cudaFuncSetAttribute(AlpamayoR1_solve_kernel,
                         cudaFuncAttributeMaxDynamicSharedMemorySize, SMEM_BYTES);
    int grid = (B + NB - 1) / NB;
    AlpamayoR1_solve_kernel<<<grid, TPB, SMEM_BYTES>>>(dxy, theta, v0, out, B);
}